// round 15
// baseline (speedup 1.0000x reference)
#include <cuda_runtime.h>
#include <cuda_fp16.h>
#include <cstdint>
#include <mma.h>
using namespace nvcuda;

// Problem dims
#define HD   2048
#define ID   16384
#define TT   8192
#define NE   5
#define RNK  16

// Scratch (device globals)
__device__ __half g_h[(size_t)TT * ID];     // gelu(g)*u intermediate, fp16 (256MB)
__device__ __half g_xh[(size_t)TT * HD];    // fp16 x (32MB)
__device__ __half g_gwh[(size_t)ID * HD];   // fp16 gate_w (64MB)
__device__ __half g_uwh[(size_t)ID * HD];   // fp16 up_w (64MB)
__device__ __half g_dwh[(size_t)HD * ID];   // fp16 down_w (64MB)
__device__ int    g_sel[TT];
__device__ float  g_probs[NE];
__device__ float  g_counts[NE];

// ---------------------------------------------------------------------------
__device__ __forceinline__ uint32_t smem_u32(const void* p) {
    return (uint32_t)__cvta_generic_to_shared(p);
}
__device__ __forceinline__ void cp16s(uint32_t saddr, const void* g) {
    asm volatile("cp.async.cg.shared.global [%0], [%1], 16;" :: "r"(saddr), "l"(g));
}
__device__ __forceinline__ void cp_commit() { asm volatile("cp.async.commit_group;"); }
template <int N> __device__ __forceinline__ void cp_wait() {
    asm volatile("cp.async.wait_group %0;" :: "n"(N));
}
__device__ __forceinline__ float fast_tanh(float x) {
    float y; asm("tanh.approx.f32 %0, %1;" : "=f"(y) : "f"(x)); return y;
}
__device__ __forceinline__ float gelu_tanh(float v) {
    const float c = 0.7978845608028654f;
    float t = c * (v + 0.044715f * v * v * v);
    return 0.5f * v * (1.0f + fast_tanh(t));
}

// ---------------------------------------------------------------------------
__global__ void k_zero() {
    int i = threadIdx.x;
    if (i < NE) { g_probs[i] = 0.0f; g_counts[i] = 0.0f; }
}

__global__ void k_cvt_h(const float4* __restrict__ src, uint2* __restrict__ dst, int n4) {
    int i = blockIdx.x * blockDim.x + threadIdx.x;
    if (i < n4) {
        float4 v = src[i];
        union { __half2 h[2]; uint2 u; } tmp;
        tmp.h[0] = __floats2half2_rn(v.x, v.y);
        tmp.h[1] = __floats2half2_rn(v.z, v.w);
        dst[i] = tmp.u;
    }
}

// router: one warp per token; ALSO writes the fp16 copy of x (fuses x-cvt).
__global__ void k_router(const float* __restrict__ x, const float* __restrict__ rw,
                         __half* __restrict__ xh) {
    __shared__ float sp[NE];
    __shared__ float sc[NE];
    int tid = threadIdx.x, warp = tid >> 5, lane = tid & 31;
    if (tid < NE) { sp[tid] = 0.0f; sc[tid] = 0.0f; }
    __syncthreads();

    int t = blockIdx.x * 8 + warp;
    float acc[NE];
#pragma unroll
    for (int e = 0; e < NE; e++) acc[e] = 0.0f;
    const float* xr = x + (size_t)t * HD;
    __half* xhr = xh + (size_t)t * HD;
    for (int h = lane * 2; h < HD; h += 64) {
        float x0 = xr[h], x1 = xr[h + 1];
        *(__half2*)(xhr + h) = __floats2half2_rn(x0, x1);
#pragma unroll
        for (int e = 0; e < NE; e++)
            acc[e] += x0 * rw[e * HD + h] + x1 * rw[e * HD + h + 1];
    }
#pragma unroll
    for (int e = 0; e < NE; e++) {
#pragma unroll
        for (int off = 16; off > 0; off >>= 1)
            acc[e] += __shfl_down_sync(0xffffffffu, acc[e], off);
    }
    if (lane == 0) {
        int sel = 0; float m = acc[0];
#pragma unroll
        for (int e = 1; e < NE; e++) if (acc[e] > m) { m = acc[e]; sel = e; }
        float s = 0.0f, p[NE];
#pragma unroll
        for (int e = 0; e < NE; e++) { p[e] = __expf(acc[e] - m); s += p[e]; }
        float inv = 1.0f / s;
#pragma unroll
        for (int e = 0; e < NE; e++) atomicAdd(&sp[e], p[e] * inv);
        atomicAdd(&sc[sel], 1.0f);
        g_sel[t] = sel;
    }
    __syncthreads();
    if (tid < NE) {
        atomicAdd(&g_probs[tid], sp[tid]);
        atomicAdd(&g_counts[tid], sc[tid]);
    }
}

__global__ void k_aux(float* __restrict__ out) {
    float a = 0.0f;
    const float invT = 1.0f / (float)TT;
#pragma unroll
    for (int e = 0; e < NE; e++)
        a += (g_probs[e] * invT) * (g_counts[e] * invT);
    out[(size_t)TT * HD] = a * (float)NE * 0.01f;
}

// ---------------------------------------------------------------------------
// gemm1 (fp16 wmma): h[t,i] = gelu(x*gate_i) * (x*up_i)
// BM=128, BN=64, BK=128; 256 threads (8 warps 4x2), warp tile 32x32 (R10 layout).
// 3 stages x 69632B = 208896B smem, 1 CTA/SM. 16 K-stages (half of R10's 32).
#define LDH    136
#define G1_STG 69632
__global__ __launch_bounds__(256, 1)
void k_gemm1(const __half* __restrict__ X,
             const __half* __restrict__ GW,
             const __half* __restrict__ UW,
             __half* __restrict__ Hout) {
    extern __shared__ __align__(16) char smem[];
    const int tid  = threadIdx.x;
    const int warp = tid >> 5;
    const int wm   = warp >> 1;        // 0..3
    const int wn   = warp & 1;         // 0..1
    const int row0 = blockIdx.x * 128;
    const int col0 = blockIdx.y * 64;

    wmma::fragment<wmma::accumulator, 16, 16, 16, float> cg[2][2], cu[2][2];
#pragma unroll
    for (int i = 0; i < 2; i++)
#pragma unroll
        for (int j = 0; j < 2; j++) {
            wmma::fill_fragment(cg[i][j], 0.0f);
            wmma::fill_fragment(cu[i][j], 0.0f);
        }

    auto prefetch = [&](int kt, int s) {
        const int k0 = kt * 128;
        __half* a  = (__half*)(smem + s * G1_STG);
        __half* bg = (__half*)(smem + s * G1_STG + 34816);
        __half* bu = (__half*)(smem + s * G1_STG + 52224);
#pragma unroll
        for (int i = 0; i < 8; i++) {            // A: 128 rows x 16 chunks
            int c = tid + i * 256;
            int r = c >> 4, kc = c & 15;
            cp16s(smem_u32(a + r * LDH + kc * 8),
                  X + (size_t)(row0 + r) * HD + k0 + kc * 8);
        }
#pragma unroll
        for (int i = 0; i < 4; i++) {            // Bg/Bu: 64 rows x 16 chunks
            int c = tid + i * 256;
            int r = c >> 4, kc = c & 15;
            cp16s(smem_u32(bg + r * LDH + kc * 8),
                  GW + (size_t)(col0 + r) * HD + k0 + kc * 8);
            cp16s(smem_u32(bu + r * LDH + kc * 8),
                  UW + (size_t)(col0 + r) * HD + k0 + kc * 8);
        }
        cp_commit();
    };

    const int NITER = HD / 128;                  // 16
    prefetch(0, 0);
    prefetch(1, 1);

    for (int it = 0; it < NITER; it++) {
        const int s = it % 3;
        cp_wait<1>();
        __syncthreads();

        const __half* a  = (const __half*)(smem + s * G1_STG);
        const __half* bg = (const __half*)(smem + s * G1_STG + 34816);
        const __half* bu = (const __half*)(smem + s * G1_STG + 52224);
#pragma unroll
        for (int kk = 0; kk < 128; kk += 16) {
            wmma::fragment<wmma::matrix_a, 16, 16, 16, __half, wmma::row_major> af[2];
            wmma::fragment<wmma::matrix_b, 16, 16, 16, __half, wmma::col_major> bf[2];
#pragma unroll
            for (int i = 0; i < 2; i++)
                wmma::load_matrix_sync(af[i], a + (wm * 32 + 16 * i) * LDH + kk, LDH);
#pragma unroll
            for (int j = 0; j < 2; j++)
                wmma::load_matrix_sync(bf[j], bg + (wn * 32 + 16 * j) * LDH + kk, LDH);
#pragma unroll
            for (int i = 0; i < 2; i++)
#pragma unroll
                for (int j = 0; j < 2; j++)
                    wmma::mma_sync(cg[i][j], af[i], bf[j], cg[i][j]);
#pragma unroll
            for (int j = 0; j < 2; j++)
                wmma::load_matrix_sync(bf[j], bu + (wn * 32 + 16 * j) * LDH + kk, LDH);
#pragma unroll
            for (int i = 0; i < 2; i++)
#pragma unroll
                for (int j = 0; j < 2; j++)
                    wmma::mma_sync(cu[i][j], af[i], bf[j], cu[i][j]);
        }

        if (it + 2 < NITER) prefetch(it + 2, (it + 2) % 3);
        else cp_commit();
    }

    // Epilogue: gelu(g)*u in-register, stage 32KB f32, emit half2.
#pragma unroll
    for (int i = 0; i < 2; i++)
#pragma unroll
        for (int j = 0; j < 2; j++)
#pragma unroll
            for (int e = 0; e < cg[i][j].num_elements; e++)
                cg[i][j].x[e] = gelu_tanh(cg[i][j].x[e]) * cu[i][j].x[e];

    __syncthreads();
    float* eg = (float*)smem;                    // 128x64 f32 = 32KB
#pragma unroll
    for (int i = 0; i < 2; i++)
#pragma unroll
        for (int j = 0; j < 2; j++)
            wmma::store_matrix_sync(eg + (wm * 32 + 16 * i) * 64 + wn * 32 + 16 * j,
                                    cg[i][j], 64, wmma::mem_row_major);
    __syncthreads();
#pragma unroll
    for (int i = 0; i < 16; i++) {
        int idx = tid + i * 256;                 // half2 unit, 0..4095
        int e = idx * 2;
        int m = e >> 6, n = e & 63;
        __half2 h = __floats2half2_rn(eg[m * 64 + n], eg[m * 64 + n + 1]);
        *(__half2*)(Hout + (size_t)(row0 + m) * ID + col0 + n) = h;
    }
}

// ---------------------------------------------------------------------------
// gemm2 (fp16 wmma): out[t,h] = h[t,:] . down_w[h,:]
// BM=128, BN=128, BK=128; 256 threads (8 warps 4x2), warp tile 32x64.
// 3 stages x 69632B, 1 CTA/SM. 128 K-stages (half of R10's 256).
#define G2_STG 69632
__global__ __launch_bounds__(256, 1)
void k_gemm2(const __half* __restrict__ Hin,
             const __half* __restrict__ DW,
             float* __restrict__ out) {
    extern __shared__ __align__(16) char smem[];
    const int tid  = threadIdx.x;
    const int warp = tid >> 5;
    const int wm   = warp >> 1;
    const int wn   = warp & 1;
    const int row0 = blockIdx.x * 128;
    const int col0 = blockIdx.y * 128;

    wmma::fragment<wmma::accumulator, 16, 16, 16, float> c[2][4];
#pragma unroll
    for (int i = 0; i < 2; i++)
#pragma unroll
        for (int j = 0; j < 4; j++)
            wmma::fill_fragment(c[i][j], 0.0f);

    auto prefetch = [&](int kt, int s) {
        const int k0 = kt * 128;
        __half* a = (__half*)(smem + s * G2_STG);
        __half* b = (__half*)(smem + s * G2_STG + 34816);
#pragma unroll
        for (int i = 0; i < 8; i++) {
            int cix = tid + i * 256;
            int r = cix >> 4, kc = cix & 15;
            cp16s(smem_u32(a + r * LDH + kc * 8),
                  Hin + (size_t)(row0 + r) * ID + k0 + kc * 8);
            cp16s(smem_u32(b + r * LDH + kc * 8),
                  DW + (size_t)(col0 + r) * ID + k0 + kc * 8);
        }
        cp_commit();
    };

    const int NITER = ID / 128;                  // 128
    prefetch(0, 0);
    prefetch(1, 1);

    for (int it = 0; it < NITER; it++) {
        const int s = it % 3;
        cp_wait<1>();
        __syncthreads();

        const __half* a = (const __half*)(smem + s * G2_STG);
        const __half* b = (const __half*)(smem + s * G2_STG + 34816);
#pragma unroll
        for (int kk = 0; kk < 128; kk += 16) {
            wmma::fragment<wmma::matrix_a, 16, 16, 16, __half, wmma::row_major> af[2];
            wmma::fragment<wmma::matrix_b, 16, 16, 16, __half, wmma::col_major> bf[4];
#pragma unroll
            for (int i = 0; i < 2; i++)
                wmma::load_matrix_sync(af[i], a + (wm * 32 + 16 * i) * LDH + kk, LDH);
#pragma unroll
            for (int j = 0; j < 4; j++)
                wmma::load_matrix_sync(bf[j], b + (wn * 64 + 16 * j) * LDH + kk, LDH);
#pragma unroll
            for (int i = 0; i < 2; i++)
#pragma unroll
                for (int j = 0; j < 4; j++)
                    wmma::mma_sync(c[i][j], af[i], bf[j], c[i][j]);
        }

        if (it + 2 < NITER) prefetch(it + 2, (it + 2) % 3);
        else cp_commit();
    }

#pragma unroll
    for (int i = 0; i < 2; i++)
#pragma unroll
        for (int j = 0; j < 4; j++) {
            float* dst = &out[(size_t)(row0 + wm * 32 + 16 * i) * HD + col0 + wn * 64 + 16 * j];
            wmma::store_matrix_sync(dst, c[i][j], HD, wmma::mem_row_major);
        }
}

// ---------------------------------------------------------------------------
// LoRA correction (fp32)
__global__ __launch_bounds__(256)
void k_lora(const float* __restrict__ x,
            const float* __restrict__ la,
            const float* __restrict__ lb,
            float* __restrict__ out) {
    const int t = blockIdx.x;
    const int sel = g_sel[t];
    if (sel == 0) return;
    const int e = sel - 1;

    __shared__ float st[RNK];
    const int tid = threadIdx.x, warp = tid >> 5, lane = tid & 31;

    const float* Ae = la + (size_t)e * RNK * HD;
    const float* xr = x + (size_t)t * HD;
    float a0 = 0.0f, a1 = 0.0f;
    for (int h = lane; h < HD; h += 32) {
        float xv = xr[h];
        a0 += xv * Ae[warp * HD + h];
        a1 += xv * Ae[(warp + 8) * HD + h];
    }
#pragma unroll
    for (int off = 16; off > 0; off >>= 1) {
        a0 += __shfl_down_sync(0xffffffffu, a0, off);
        a1 += __shfl_down_sync(0xffffffffu, a1, off);
    }
    if (lane == 0) { st[warp] = a0; st[warp + 8] = a1; }
    __syncthreads();

    const float* Be = lb + (size_t)e * HD * RNK;
    float* orow = out + (size_t)t * HD;
    for (int h = tid; h < HD; h += 256) {
        float acc = 0.0f;
        const float4* b4 = (const float4*)&Be[h * RNK];
#pragma unroll
        for (int q = 0; q < 4; q++) {
            float4 bv = b4[q];
            acc += st[q * 4 + 0] * bv.x + st[q * 4 + 1] * bv.y +
                   st[q * 4 + 2] * bv.z + st[q * 4 + 3] * bv.w;
        }
        orow[h] += 2.0f * acc;
    }
}

// ---------------------------------------------------------------------------
extern "C" void kernel_launch(void* const* d_in, const int* in_sizes, int n_in,
                              void* d_out, int out_size) {
    const float* x  = (const float*)d_in[0];
    const float* rw = (const float*)d_in[1];
    const float* gw = (const float*)d_in[2];
    const float* uw = (const float*)d_in[3];
    const float* dw = (const float*)d_in[4];
    const float* la = (const float*)d_in[5];
    const float* lb = (const float*)d_in[6];
    float* out = (float*)d_out;

    const int SMEM1 = 3 * G1_STG;   // 208896 B
    const int SMEM2 = 3 * G2_STG;   // 208896 B
    cudaFuncSetAttribute(k_gemm1, cudaFuncAttributeMaxDynamicSharedMemorySize, SMEM1);
    cudaFuncSetAttribute(k_gemm2, cudaFuncAttributeMaxDynamicSharedMemorySize, SMEM2);

    __half* p_xh;  cudaGetSymbolAddress((void**)&p_xh,  g_xh);
    __half* p_gwh; cudaGetSymbolAddress((void**)&p_gwh, g_gwh);
    __half* p_uwh; cudaGetSymbolAddress((void**)&p_uwh, g_uwh);
    __half* p_dwh; cudaGetSymbolAddress((void**)&p_dwh, g_dwh);
    __half* p_h;   cudaGetSymbolAddress((void**)&p_h,   g_h);

    k_zero<<<1, 32>>>();
    k_router<<<TT / 8, 256>>>(x, rw, p_xh);   // also emits fp16 x
    k_aux<<<1, 1>>>(out);

    {
        int n4w = ID * HD / 4;
        k_cvt_h<<<n4w / 256, 256>>>((const float4*)gw, (uint2*)p_gwh, n4w);
        k_cvt_h<<<n4w / 256, 256>>>((const float4*)uw, (uint2*)p_uwh, n4w);
        k_cvt_h<<<n4w / 256, 256>>>((const float4*)dw, (uint2*)p_dwh, n4w);
    }

    dim3 g1(TT / 128, ID / 64);          // token tile fast: x resident in L2
    k_gemm1<<<g1, 256, SMEM1>>>(p_xh, p_gwh, p_uwh, p_h);

    dim3 g2(TT / 128, HD / 128);         // token tile fast: dw panel reused
    k_gemm2<<<g2, 256, SMEM2>>>(p_h, p_dwh, out);

    k_lora<<<TT, 256>>>(x, la, lb, out);
}

// round 16
// speedup vs baseline: 1.1675x; 1.1675x over previous
#include <cuda_runtime.h>
#include <cuda_fp16.h>
#include <cstdint>
#include <mma.h>
using namespace nvcuda;

// Problem dims
#define HD   2048
#define ID   16384
#define TT   8192
#define NE   5
#define RNK  16

// Scratch (device globals)
__device__ __half g_h[(size_t)TT * ID];     // gelu(g)*u intermediate, fp16 (256MB)
__device__ __half g_xh[(size_t)TT * HD];    // fp16 x (32MB)
__device__ __half g_gwh[(size_t)ID * HD];   // fp16 gate_w (64MB)
__device__ __half g_uwh[(size_t)ID * HD];   // fp16 up_w (64MB)
__device__ __half g_dwh[(size_t)HD * ID];   // fp16 down_w (64MB)
__device__ int    g_sel[TT];
__device__ float  g_probs[NE];
__device__ float  g_counts[NE];

// ---------------------------------------------------------------------------
__device__ __forceinline__ uint32_t smem_u32(const void* p) {
    return (uint32_t)__cvta_generic_to_shared(p);
}
__device__ __forceinline__ void cp16s(uint32_t saddr, const void* g) {
    asm volatile("cp.async.cg.shared.global [%0], [%1], 16;" :: "r"(saddr), "l"(g));
}
__device__ __forceinline__ void cp_commit() { asm volatile("cp.async.commit_group;"); }
template <int N> __device__ __forceinline__ void cp_wait() {
    asm volatile("cp.async.wait_group %0;" :: "n"(N));
}
__device__ __forceinline__ float fast_tanh(float x) {
    float y; asm("tanh.approx.f32 %0, %1;" : "=f"(y) : "f"(x)); return y;
}
__device__ __forceinline__ float gelu_tanh(float v) {
    const float c = 0.7978845608028654f;
    float t = c * (v + 0.044715f * v * v * v);
    return 0.5f * v * (1.0f + fast_tanh(t));
}

// ---------------------------------------------------------------------------
__global__ void k_zero() {
    int i = threadIdx.x;
    if (i < NE) { g_probs[i] = 0.0f; g_counts[i] = 0.0f; }
}

__global__ void k_cvt_h(const float4* __restrict__ src, uint2* __restrict__ dst, int n4) {
    int i = blockIdx.x * blockDim.x + threadIdx.x;
    if (i < n4) {
        float4 v = src[i];
        union { __half2 h[2]; uint2 u; } tmp;
        tmp.h[0] = __floats2half2_rn(v.x, v.y);
        tmp.h[1] = __floats2half2_rn(v.z, v.w);
        dst[i] = tmp.u;
    }
}

// router: one warp per token; ALSO writes the fp16 copy of x (fuses x-cvt).
__global__ void k_router(const float* __restrict__ x, const float* __restrict__ rw,
                         __half* __restrict__ xh) {
    __shared__ float sp[NE];
    __shared__ float sc[NE];
    int tid = threadIdx.x, warp = tid >> 5, lane = tid & 31;
    if (tid < NE) { sp[tid] = 0.0f; sc[tid] = 0.0f; }
    __syncthreads();

    int t = blockIdx.x * 8 + warp;
    float acc[NE];
#pragma unroll
    for (int e = 0; e < NE; e++) acc[e] = 0.0f;
    const float* xr = x + (size_t)t * HD;
    __half* xhr = xh + (size_t)t * HD;
    for (int h = lane * 2; h < HD; h += 64) {
        float x0 = xr[h], x1 = xr[h + 1];
        *(__half2*)(xhr + h) = __floats2half2_rn(x0, x1);
#pragma unroll
        for (int e = 0; e < NE; e++)
            acc[e] += x0 * rw[e * HD + h] + x1 * rw[e * HD + h + 1];
    }
#pragma unroll
    for (int e = 0; e < NE; e++) {
#pragma unroll
        for (int off = 16; off > 0; off >>= 1)
            acc[e] += __shfl_down_sync(0xffffffffu, acc[e], off);
    }
    if (lane == 0) {
        int sel = 0; float m = acc[0];
#pragma unroll
        for (int e = 1; e < NE; e++) if (acc[e] > m) { m = acc[e]; sel = e; }
        float s = 0.0f, p[NE];
#pragma unroll
        for (int e = 0; e < NE; e++) { p[e] = __expf(acc[e] - m); s += p[e]; }
        float inv = 1.0f / s;
#pragma unroll
        for (int e = 0; e < NE; e++) atomicAdd(&sp[e], p[e] * inv);
        atomicAdd(&sc[sel], 1.0f);
        g_sel[t] = sel;
    }
    __syncthreads();
    if (tid < NE) {
        atomicAdd(&g_probs[tid], sp[tid]);
        atomicAdd(&g_counts[tid], sc[tid]);
    }
}

__global__ void k_aux(float* __restrict__ out) {
    float a = 0.0f;
    const float invT = 1.0f / (float)TT;
#pragma unroll
    for (int e = 0; e < NE; e++)
        a += (g_probs[e] * invT) * (g_counts[e] * invT);
    out[(size_t)TT * HD] = a * (float)NE * 0.01f;
}

// ---------------------------------------------------------------------------
// gemm1 (fp16 wmma, R10 config): h[t,i] = gelu(x*gate_i) * (x*up_i)
// BM=128, BN=64, BK=64; 256 threads (8 warps 4x2), warp tile 32x32 (g+u).
// 3-stage cp.async; stage = A 128x72h + Bg 64x72h + Bu 64x72h = 36864B; 2 CTA/SM.
#define G1_STG 36864
#define LDH    72
__global__ __launch_bounds__(256, 2)
void k_gemm1(const __half* __restrict__ X,
             const __half* __restrict__ GW,
             const __half* __restrict__ UW,
             __half* __restrict__ Hout) {
    extern __shared__ __align__(16) char smem[];
    const int tid  = threadIdx.x;
    const int warp = tid >> 5;
    const int wm   = warp >> 1;        // 0..3
    const int wn   = warp & 1;         // 0..1
    const int row0 = blockIdx.x * 128; // token tile
    const int col0 = blockIdx.y * 64;  // intermediate tile

    wmma::fragment<wmma::accumulator, 16, 16, 16, float> cg[2][2], cu[2][2];
#pragma unroll
    for (int i = 0; i < 2; i++)
#pragma unroll
        for (int j = 0; j < 2; j++) {
            wmma::fill_fragment(cg[i][j], 0.0f);
            wmma::fill_fragment(cu[i][j], 0.0f);
        }

    auto prefetch = [&](int kt, int s) {
        const int k0 = kt * 64;
        __half* a  = (__half*)(smem + s * G1_STG);
        __half* bg = (__half*)(smem + s * G1_STG + 18432);
        __half* bu = (__half*)(smem + s * G1_STG + 27648);
#pragma unroll
        for (int i = 0; i < 4; i++) {
            int c = tid + i * 256;          // 0..1023
            int r = c >> 3, kc = c & 7;
            cp16s(smem_u32(a + r * LDH + kc * 8),
                  X + (size_t)(row0 + r) * HD + k0 + kc * 8);
        }
#pragma unroll
        for (int i = 0; i < 2; i++) {
            int c = tid + i * 256;          // 0..511
            int r = c >> 3, kc = c & 7;
            cp16s(smem_u32(bg + r * LDH + kc * 8),
                  GW + (size_t)(col0 + r) * HD + k0 + kc * 8);
            cp16s(smem_u32(bu + r * LDH + kc * 8),
                  UW + (size_t)(col0 + r) * HD + k0 + kc * 8);
        }
        cp_commit();
    };

    const int NITER = HD / 64;             // 32
    prefetch(0, 0);
    prefetch(1, 1);

    for (int it = 0; it < NITER; it++) {
        const int s = it % 3;
        cp_wait<1>();
        __syncthreads();

        const __half* a  = (const __half*)(smem + s * G1_STG);
        const __half* bg = (const __half*)(smem + s * G1_STG + 18432);
        const __half* bu = (const __half*)(smem + s * G1_STG + 27648);
#pragma unroll
        for (int kk = 0; kk < 64; kk += 16) {
            wmma::fragment<wmma::matrix_a, 16, 16, 16, __half, wmma::row_major> af[2];
            wmma::fragment<wmma::matrix_b, 16, 16, 16, __half, wmma::col_major> bf[2];
#pragma unroll
            for (int i = 0; i < 2; i++)
                wmma::load_matrix_sync(af[i], a + (wm * 32 + 16 * i) * LDH + kk, LDH);
#pragma unroll
            for (int j = 0; j < 2; j++)
                wmma::load_matrix_sync(bf[j], bg + (wn * 32 + 16 * j) * LDH + kk, LDH);
#pragma unroll
            for (int i = 0; i < 2; i++)
#pragma unroll
                for (int j = 0; j < 2; j++)
                    wmma::mma_sync(cg[i][j], af[i], bf[j], cg[i][j]);
#pragma unroll
            for (int j = 0; j < 2; j++)
                wmma::load_matrix_sync(bf[j], bu + (wn * 32 + 16 * j) * LDH + kk, LDH);
#pragma unroll
            for (int i = 0; i < 2; i++)
#pragma unroll
                for (int j = 0; j < 2; j++)
                    wmma::mma_sync(cu[i][j], af[i], bf[j], cu[i][j]);
        }

        if (it + 2 < NITER) prefetch(it + 2, (it + 2) % 3);
        else cp_commit();
    }

    // Epilogue: gelu(g)*u in-register, one 32KB f32 staging pass, half2 stores.
#pragma unroll
    for (int i = 0; i < 2; i++)
#pragma unroll
        for (int j = 0; j < 2; j++)
#pragma unroll
            for (int e = 0; e < cg[i][j].num_elements; e++)
                cg[i][j].x[e] = gelu_tanh(cg[i][j].x[e]) * cu[i][j].x[e];

    __syncthreads();
    float* eg = (float*)smem;                 // 128x64 f32 = 32KB
#pragma unroll
    for (int i = 0; i < 2; i++)
#pragma unroll
        for (int j = 0; j < 2; j++)
            wmma::store_matrix_sync(eg + (wm * 32 + 16 * i) * 64 + wn * 32 + 16 * j,
                                    cg[i][j], 64, wmma::mem_row_major);
    __syncthreads();
#pragma unroll
    for (int i = 0; i < 16; i++) {
        int idx = tid + i * 256;              // half2 unit, 0..4095
        int e = idx * 2;
        int m = e >> 6, n = e & 63;
        __half2 h = __floats2half2_rn(eg[m * 64 + n], eg[m * 64 + n + 1]);
        *(__half2*)(Hout + (size_t)(row0 + m) * ID + col0 + n) = h;
    }
}

// ---------------------------------------------------------------------------
// gemm2 (fp16 wmma, R10 config): out[t,h] = h[t,:] . down_w[h,:]
// BM=128, BN=128, BK=64; 256 threads (8 warps 4x2), warp tile 32x64; 2 CTA/SM.
#define G2_STG 36864
__global__ __launch_bounds__(256, 2)
void k_gemm2(const __half* __restrict__ Hin,
             const __half* __restrict__ DW,
             float* __restrict__ out) {
    extern __shared__ __align__(16) char smem[];
    const int tid  = threadIdx.x;
    const int warp = tid >> 5;
    const int wm   = warp >> 1;
    const int wn   = warp & 1;
    const int row0 = blockIdx.x * 128;  // token tile
    const int col0 = blockIdx.y * 128;  // hidden tile

    wmma::fragment<wmma::accumulator, 16, 16, 16, float> c[2][4];
#pragma unroll
    for (int i = 0; i < 2; i++)
#pragma unroll
        for (int j = 0; j < 4; j++)
            wmma::fill_fragment(c[i][j], 0.0f);

    auto prefetch = [&](int kt, int s) {
        const int k0 = kt * 64;
        __half* a = (__half*)(smem + s * G2_STG);
        __half* b = (__half*)(smem + s * G2_STG + 18432);
#pragma unroll
        for (int i = 0; i < 4; i++) {
            int cix = tid + i * 256;        // 0..1023
            int r = cix >> 3, kc = cix & 7;
            cp16s(smem_u32(a + r * LDH + kc * 8),
                  Hin + (size_t)(row0 + r) * ID + k0 + kc * 8);
            cp16s(smem_u32(b + r * LDH + kc * 8),
                  DW + (size_t)(col0 + r) * ID + k0 + kc * 8);
        }
        cp_commit();
    };

    const int NITER = ID / 64;              // 256
    prefetch(0, 0);
    prefetch(1, 1);

    for (int it = 0; it < NITER; it++) {
        const int s = it % 3;
        cp_wait<1>();
        __syncthreads();

        const __half* a = (const __half*)(smem + s * G2_STG);
        const __half* b = (const __half*)(smem + s * G2_STG + 18432);
#pragma unroll
        for (int kk = 0; kk < 64; kk += 16) {
            wmma::fragment<wmma::matrix_a, 16, 16, 16, __half, wmma::row_major> af[2];
            wmma::fragment<wmma::matrix_b, 16, 16, 16, __half, wmma::col_major> bf[4];
#pragma unroll
            for (int i = 0; i < 2; i++)
                wmma::load_matrix_sync(af[i], a + (wm * 32 + 16 * i) * LDH + kk, LDH);
#pragma unroll
            for (int j = 0; j < 4; j++)
                wmma::load_matrix_sync(bf[j], b + (wn * 64 + 16 * j) * LDH + kk, LDH);
#pragma unroll
            for (int i = 0; i < 2; i++)
#pragma unroll
                for (int j = 0; j < 4; j++)
                    wmma::mma_sync(c[i][j], af[i], bf[j], c[i][j]);
        }

        if (it + 2 < NITER) prefetch(it + 2, (it + 2) % 3);
        else cp_commit();
    }

#pragma unroll
    for (int i = 0; i < 2; i++)
#pragma unroll
        for (int j = 0; j < 4; j++) {
            float* dst = &out[(size_t)(row0 + wm * 32 + 16 * i) * HD + col0 + wn * 64 + 16 * j];
            wmma::store_matrix_sync(dst, c[i][j], HD, wmma::mem_row_major);
        }
}

// ---------------------------------------------------------------------------
// LoRA correction (fp32)
__global__ __launch_bounds__(256)
void k_lora(const float* __restrict__ x,
            const float* __restrict__ la,
            const float* __restrict__ lb,
            float* __restrict__ out) {
    const int t = blockIdx.x;
    const int sel = g_sel[t];
    if (sel == 0) return;
    const int e = sel - 1;

    __shared__ float st[RNK];
    const int tid = threadIdx.x, warp = tid >> 5, lane = tid & 31;

    const float* Ae = la + (size_t)e * RNK * HD;
    const float* xr = x + (size_t)t * HD;
    float a0 = 0.0f, a1 = 0.0f;
    for (int h = lane; h < HD; h += 32) {
        float xv = xr[h];
        a0 += xv * Ae[warp * HD + h];
        a1 += xv * Ae[(warp + 8) * HD + h];
    }
#pragma unroll
    for (int off = 16; off > 0; off >>= 1) {
        a0 += __shfl_down_sync(0xffffffffu, a0, off);
        a1 += __shfl_down_sync(0xffffffffu, a1, off);
    }
    if (lane == 0) { st[warp] = a0; st[warp + 8] = a1; }
    __syncthreads();

    const float* Be = lb + (size_t)e * HD * RNK;
    float* orow = out + (size_t)t * HD;
    for (int h = tid; h < HD; h += 256) {
        float acc = 0.0f;
        const float4* b4 = (const float4*)&Be[h * RNK];
#pragma unroll
        for (int q = 0; q < 4; q++) {
            float4 bv = b4[q];
            acc += st[q * 4 + 0] * bv.x + st[q * 4 + 1] * bv.y +
                   st[q * 4 + 2] * bv.z + st[q * 4 + 3] * bv.w;
        }
        orow[h] += 2.0f * acc;
    }
}

// ---------------------------------------------------------------------------
extern "C" void kernel_launch(void* const* d_in, const int* in_sizes, int n_in,
                              void* d_out, int out_size) {
    const float* x  = (const float*)d_in[0];
    const float* rw = (const float*)d_in[1];
    const float* gw = (const float*)d_in[2];
    const float* uw = (const float*)d_in[3];
    const float* dw = (const float*)d_in[4];
    const float* la = (const float*)d_in[5];
    const float* lb = (const float*)d_in[6];
    float* out = (float*)d_out;

    const int SMEM1 = 3 * G1_STG;   // 110592 B
    const int SMEM2 = 3 * G2_STG;   // 110592 B
    cudaFuncSetAttribute(k_gemm1, cudaFuncAttributeMaxDynamicSharedMemorySize, SMEM1);
    cudaFuncSetAttribute(k_gemm2, cudaFuncAttributeMaxDynamicSharedMemorySize, SMEM2);

    __half* p_xh;  cudaGetSymbolAddress((void**)&p_xh,  g_xh);
    __half* p_gwh; cudaGetSymbolAddress((void**)&p_gwh, g_gwh);
    __half* p_uwh; cudaGetSymbolAddress((void**)&p_uwh, g_uwh);
    __half* p_dwh; cudaGetSymbolAddress((void**)&p_dwh, g_dwh);
    __half* p_h;   cudaGetSymbolAddress((void**)&p_h,   g_h);

    int n4w = ID * HD / 4;                         // 8,388,608

    // Launch order chosen so ncu (-s 5 -c 1) profiles k_gemm1 as launch #6.
    k_zero<<<1, 32>>>();                                          // 1
    k_router<<<TT / 8, 256>>>(x, rw, p_xh);                       // 2 (emits fp16 x)
    k_aux<<<1, 1>>>(out);                                         // 3
    k_cvt_h<<<n4w / 256, 256>>>((const float4*)gw, (uint2*)p_gwh, n4w);  // 4
    k_cvt_h<<<n4w / 256, 256>>>((const float4*)uw, (uint2*)p_uwh, n4w);  // 5

    dim3 g1(TT / 128, ID / 64);
    k_gemm1<<<g1, 256, SMEM1>>>(p_xh, p_gwh, p_uwh, p_h);         // 6 <- profiled

    k_cvt_h<<<n4w / 256, 256>>>((const float4*)dw, (uint2*)p_dwh, n4w);  // 7

    dim3 g2(TT / 128, HD / 128);
    k_gemm2<<<g2, 256, SMEM2>>>(p_h, p_dwh, out);                 // 8

    k_lora<<<TT, 256>>>(x, la, lb, out);                          // 9
}